// round 13
// baseline (speedup 1.0000x reference)
#include <cuda_runtime.h>
#include <cuda_fp16.h>
#include <math.h>
#include <float.h>

#define NROWS 200000
#define NBAGS 25000
#define DIM   690
#define NREL  53
#define NPAD  56           // P row stride (cols 53..55 unused)
#define NKS   44           // k16 steps (704 / 16)
#define NJ    7            // n-tiles (56 cols)
#define WCAP  128
#define HROWS 100000       // rows per k_pgemm launch (2 launches)

// ---------------- scratch (device globals: allocation-free) ----------------
__device__ __align__(16) float g_P[(size_t)NROWS * NPAD];       // 44.8 MB
__device__ __align__(8) uint2 g_Bpack[NKS * NJ * 32];           // 79 KB hi-frag table
__device__ float g_wglob[NROWS];

// ---------------- PTX helpers ----------------
__device__ __forceinline__ void mma_f16(float* c, const unsigned* a, const unsigned* b) {
    asm volatile(
        "mma.sync.aligned.m16n8k16.row.col.f32.f16.f16.f32 "
        "{%0,%1,%2,%3}, {%4,%5,%6,%7}, {%8,%9}, {%0,%1,%2,%3};"
        : "+f"(c[0]), "+f"(c[1]), "+f"(c[2]), "+f"(c[3])
        : "r"(a[0]), "r"(a[1]), "r"(a[2]), "r"(a[3]), "r"(b[0]), "r"(b[1]));
}
__device__ __forceinline__ unsigned packh2(float x, float y) {
    unsigned r;
    asm("cvt.rn.f16x2.f32 %0, %1, %2;" : "=r"(r) : "f"(y), "f"(x));
    return r;
}

// ---------------- K0: pack B = rel into per-lane MMA hi-fragment table -----
// entry (ks, j, lane): n = j*8 + (lane>>2), k = ks*16 + (lane&3)*2
//   .x = fp16(B[k],B[k+1])  .y = fp16(B[k+8],B[k+9])
__global__ void k_prep(const float* __restrict__ rel) {
    int idx = blockIdx.x * blockDim.x + threadIdx.x;
    if (idx >= NKS * NJ * 32) return;
    int ks = idx / (NJ * 32), rem = idx % (NJ * 32);
    int j = rem / 32, lane = rem % 32;
    int n = j * 8 + (lane >> 2);
    int k = ks * 16 + (lane & 3) * 2;
    float v[4] = {0.f, 0.f, 0.f, 0.f};
    if (n < NREL) {
        if (k < DIM)     v[0] = rel[n * DIM + k];
        if (k + 1 < DIM) v[1] = rel[n * DIM + k + 1];
        if (k + 8 < DIM) v[2] = rel[n * DIM + k + 8];
        if (k + 9 < DIM) v[3] = rel[n * DIM + k + 9];
    }
    uint2 o;
    o.x = packh2(v[0], v[1]);
    o.y = packh2(v[2], v[3]);
    g_Bpack[idx] = o;
}

// ---------------- K1: P = repre @ rel^T — barrier-free, smem-free ----------
// one warp per 16-row strip; hi-only B (7 MMA/iter). Launched twice (row halves).
__global__ __launch_bounds__(256) void k_pgemm(const float* __restrict__ repre,
                                               int strip0, int nstrips) {
    int wid = threadIdx.x >> 5, lane = threadIdx.x & 31;
    int ws = blockIdx.x * 8 + wid;
    if (ws >= nstrips) return;
    int row0 = (strip0 + ws) * 16;
    int g = lane >> 2, th = lane & 3;
    int r0 = row0 + g, r1 = r0 + 8;              // always in-bounds (200000 % 16 == 0)
    const float* p0 = repre + (size_t)r0 * DIM;
    const float* p1 = repre + (size_t)r1 * DIM;

    float acc[NJ][4];
#pragma unroll
    for (int j = 0; j < NJ; j++)
#pragma unroll
        for (int q = 0; q < 4; q++) acc[j][q] = 0.f;

    const uint2* bp_lane = g_Bpack + lane;

    // ---- main loop: ks 0..42, all columns in-bounds (max 687 < 690) ----
#pragma unroll 2
    for (int ks = 0; ks < NKS - 1; ks++) {
        int c0 = ks * 16 + th * 2;
        int c1 = c0 + 8;
        float2 v0 = *(const float2*)(p0 + c0);
        float2 v1 = *(const float2*)(p1 + c0);
        float2 v2 = *(const float2*)(p0 + c1);
        float2 v3 = *(const float2*)(p1 + c1);
        unsigned a[4];
        a[0] = packh2(v0.x, v0.y);
        a[1] = packh2(v1.x, v1.y);
        a[2] = packh2(v2.x, v2.y);
        a[3] = packh2(v3.x, v3.y);

        const uint2* bp = bp_lane + (size_t)ks * NJ * 32;
#pragma unroll
        for (int j = 0; j < NJ; j++) {
            uint2 b = bp[j * 32];
            unsigned bb[2] = {b.x, b.y};
            mma_f16(acc[j], a, bb);
        }
    }

    // ---- tail: ks = 43, only cols 688..689 (th == 0) ----
    {
        int ks = NKS - 1;
        int c0 = ks * 16 + th * 2;
        bool v = (c0 + 1 < DIM);
        float2 z = make_float2(0.f, 0.f);
        float2 v0 = v ? *(const float2*)(p0 + c0) : z;
        float2 v1 = v ? *(const float2*)(p1 + c0) : z;
        unsigned a[4];
        a[0] = packh2(v0.x, v0.y);
        a[1] = packh2(v1.x, v1.y);
        a[2] = 0u; a[3] = 0u;
        const uint2* bp = bp_lane + (size_t)ks * NJ * 32;
#pragma unroll
        for (int j = 0; j < NJ; j++) {
            uint2 b = bp[j * 32];
            unsigned bb[2] = {b.x, b.y};
            mma_f16(acc[j], a, bb);
        }
    }

    // ---- epilogue: write P ----
    size_t o0 = (size_t)r0 * NPAD;
    size_t o1 = (size_t)r1 * NPAD;
#pragma unroll
    for (int j = 0; j < NJ; j++) {
        int col = j * 8 + th * 2;
        *(float2*)&g_P[o0 + col] = make_float2(acc[j][0], acc[j][1]);
        *(float2*)&g_P[o1 + col] = make_float2(acc[j][2], acc[j][3]);
    }
}

// ---------------- K2: per-bag softmax + combine over P ---------------------
__global__ __launch_bounds__(256) void k_bags(const int* __restrict__ scope,
                                              const int* __restrict__ labels,
                                              const float* __restrict__ bias,
                                              float* __restrict__ out) {
    __shared__ float wbuf[8][WCAP];
    int wid = threadIdx.x >> 5, lane = threadIdx.x & 31;
    int bag = blockIdx.x * 8 + wid;
    if (bag >= NBAGS) return;
    int s = scope[2 * bag];
    int e = scope[2 * bag + 1];
    int c = e - s;
    float* w = (c <= WCAP) ? wbuf[wid] : (g_wglob + s);

    float m = -FLT_MAX;
    for (int i = lane; i < c; i += 32) {
        int gi = s + i;
        float lg = g_P[(size_t)gi * NPAD + labels[gi]];
        w[i] = lg;
        m = fmaxf(m, lg);
    }
#pragma unroll
    for (int o = 16; o; o >>= 1) m = fmaxf(m, __shfl_xor_sync(0xffffffffu, m, o));

    float sum = 0.f;
    for (int i = lane; i < c; i += 32) {
        float ev = __expf(w[i] - m);
        w[i] = ev;
        sum += ev;
    }
#pragma unroll
    for (int o = 16; o; o >>= 1) sum += __shfl_xor_sync(0xffffffffu, sum, o);
    float inv = 1.f / sum;
    __syncwarp();

    int col = lane * 2;
    if (col < NPAD) {    // lanes 0..27
        float2 o2 = make_float2(0.f, 0.f);
        const float* pbase = g_P + (size_t)s * NPAD + col;
#pragma unroll 8
        for (int i = 0; i < c; i++) {
            float wi = w[i] * inv;
            float2 p2 = *(const float2*)(pbase + (size_t)i * NPAD);
            o2.x = fmaf(wi, p2.x, o2.x);
            o2.y = fmaf(wi, p2.y, o2.y);
        }
        if (col < NREL)     out[(size_t)bag * NREL + col]     = o2.x + bias[col];
        if (col + 1 < NREL) out[(size_t)bag * NREL + col + 1] = o2.y + bias[col + 1];
    }
}

// ---------------- launch ----------------
extern "C" void kernel_launch(void* const* d_in, const int* in_sizes, int n_in,
                              void* d_out, int out_size) {
    const float* repre  = (const float*)d_in[0];   // [N, D]
    const float* rel    = (const float*)d_in[1];   // [R, D]
    const float* bias   = (const float*)d_in[2];   // [R]
    const int* scope    = (const int*)d_in[3];     // [NBAGS, 2] int32
    const int* labels   = (const int*)d_in[4];     // [N]        int32
    float* out = (float*)d_out;                    // [NBAGS, R]

    (void)in_sizes; (void)n_in; (void)out_size;

    k_prep<<<(NKS * NJ * 32 + 255) / 256, 256>>>(rel);
    int half_strips = HROWS / 16;                  // 6250 strips per launch
    k_pgemm<<<(half_strips + 7) / 8, 256>>>(repre, 0, half_strips);
    k_pgemm<<<(half_strips + 7) / 8, 256>>>(repre, half_strips, half_strips);
    k_bags<<<(NBAGS + 7) / 8, 256>>>(scope, labels, bias, out);
}

// round 16
// speedup vs baseline: 1.1374x; 1.1374x over previous
#include <cuda_runtime.h>
#include <cuda_fp16.h>
#include <math.h>
#include <float.h>

#define NROWS 200000
#define NBAGS 25000
#define DIM   690
#define NREL  53
#define NPAD  56           // P row stride (cols 53..55 unused)
#define NKS   44           // k16 steps (704 / 16)
#define NCH   22           // k32 chunks
#define NJ    7            // n-tiles (56 cols)
#define WCAP  128
#define SPITCH 36          // smem stage pitch (floats) per row
#define STAGE_F (16 * SPITCH)          // floats per stage (576)
#define WARP_F  (2 * STAGE_F)          // per-warp floats (1152)

// ---------------- scratch (device globals: allocation-free) ----------------
__device__ __align__(16) float g_P[(size_t)NROWS * NPAD];       // 44.8 MB
__device__ __align__(16) uint4 g_Bpack[NKS * NJ * 32];          // 158 KB frag table
__device__ float g_wglob[NROWS];

// ---------------- PTX helpers ----------------
__device__ __forceinline__ void mma_f16(float* c, const unsigned* a, const unsigned* b) {
    asm volatile(
        "mma.sync.aligned.m16n8k16.row.col.f32.f16.f16.f32 "
        "{%0,%1,%2,%3}, {%4,%5,%6,%7}, {%8,%9}, {%0,%1,%2,%3};"
        : "+f"(c[0]), "+f"(c[1]), "+f"(c[2]), "+f"(c[3])
        : "r"(a[0]), "r"(a[1]), "r"(a[2]), "r"(a[3]), "r"(b[0]), "r"(b[1]));
}
__device__ __forceinline__ unsigned packh2(float x, float y) {
    unsigned r;
    asm("cvt.rn.f16x2.f32 %0, %1, %2;" : "=r"(r) : "f"(y), "f"(x));
    return r;
}
__device__ __forceinline__ void cp8z(unsigned dst, const void* src, int bytes) {
    asm volatile("cp.async.ca.shared.global [%0], [%1], 8, %2;"
                 :: "r"(dst), "l"(src), "r"(bytes));
}
__device__ __forceinline__ void cp_commit() {
    asm volatile("cp.async.commit_group;" ::: "memory");
}
__device__ __forceinline__ void cp_wait1() {
    asm volatile("cp.async.wait_group 1;" ::: "memory");
}

// ---------------- K0: pack B = rel into per-lane MMA fragment table --------
// entry (ks, j, lane): n = j*8 + (lane>>2), k = ks*16 + (lane&3)*2
//   .x = hi(B[k],B[k+1])  .y = hi(B[k+8],B[k+9])  .z/.w = fp16 residuals
__global__ void k_prep(const float* __restrict__ rel) {
    int idx = blockIdx.x * blockDim.x + threadIdx.x;
    if (idx >= NKS * NJ * 32) return;
    int ks = idx / (NJ * 32), rem = idx % (NJ * 32);
    int j = rem / 32, lane = rem % 32;
    int n = j * 8 + (lane >> 2);
    int k = ks * 16 + (lane & 3) * 2;
    float v[4] = {0.f, 0.f, 0.f, 0.f};
    if (n < NREL) {
        if (k < DIM)     v[0] = rel[n * DIM + k];
        if (k + 1 < DIM) v[1] = rel[n * DIM + k + 1];
        if (k + 8 < DIM) v[2] = rel[n * DIM + k + 8];
        if (k + 9 < DIM) v[3] = rel[n * DIM + k + 9];
    }
    float h[4], l[4];
#pragma unroll
    for (int i = 0; i < 4; i++) {
        h[i] = __half2float(__float2half(v[i]));
        l[i] = v[i] - h[i];
    }
    uint4 o;
    o.x = packh2(h[0], h[1]);
    o.y = packh2(h[2], h[3]);
    o.z = packh2(l[0], l[1]);
    o.w = packh2(l[2], l[3]);
    g_Bpack[idx] = o;
}

// ---------------- K1: P = repre @ rel^T — per-warp cp.async pipeline -------
// one warp per 16-row strip; warp-private double-buffered A stage; no CTA sync
__global__ __launch_bounds__(256) void k_pgemm(const float* __restrict__ repre) {
    __shared__ __align__(16) float sA[8 * WARP_F];   // 36864 B

    int tid = threadIdx.x, wid = tid >> 5, lane = tid & 31;
    int w = blockIdx.x * 8 + wid;                    // strip index
    if (w >= NROWS / 16) return;
    int row0 = w * 16;
    int g = lane >> 2, th = lane & 3;

    // staging geometry: lane covers row lr (2 lanes/row), 8x 8B ops
    int lr = lane >> 1, hf = lane & 1;
    const float* srow = repre + (size_t)(row0 + lr) * DIM;   // 8B-aligned
    unsigned swbase = (unsigned)__cvta_generic_to_shared(sA + wid * WARP_F);
    unsigned dstbase = swbase + (unsigned)((lr * SPITCH + hf * 16) * 4);

    float acc[NJ][4];
#pragma unroll
    for (int j = 0; j < NJ; j++)
#pragma unroll
        for (int q = 0; q < 4; q++) acc[j][q] = 0.f;

    const uint4* bp_lane = g_Bpack + lane;

    auto issue = [&](int c) {
        unsigned d = dstbase + (unsigned)((c & 1) * STAGE_F * 4);
        int kbase = c * 32 + hf * 16;
#pragma unroll
        for (int i = 0; i < 8; i++) {
            int kf = kbase + i * 2;                       // even -> 8B-aligned src
            int bytes = max(0, min(8, (DIM - kf) * 4));
            const float* sp = srow + (bytes > 0 ? kf : 0);
            cp8z(d + i * 8, sp, bytes);
        }
    };

    issue(0); cp_commit();
    issue(1); cp_commit();

    for (int c = 0; c < NCH; c++) {
        cp_wait1();
        __syncwarp();
        unsigned stg = swbase + (unsigned)((c & 1) * STAGE_F * 4);

#pragma unroll
        for (int ks2 = 0; ks2 < 2; ks2++) {
            // A fragment via LDS.64 from warp-private stage
            unsigned r0a = stg + (unsigned)((g * SPITCH + ks2 * 16 + th * 2) * 4);
            unsigned r1a = r0a + (unsigned)(8 * SPITCH * 4);
            float2 v0, v1, v2, v3;
            asm volatile("ld.shared.v2.f32 {%0,%1}, [%2];"
                         : "=f"(v0.x), "=f"(v0.y) : "r"(r0a));
            asm volatile("ld.shared.v2.f32 {%0,%1}, [%2];"
                         : "=f"(v1.x), "=f"(v1.y) : "r"(r1a));
            asm volatile("ld.shared.v2.f32 {%0,%1}, [%2];"
                         : "=f"(v2.x), "=f"(v2.y) : "r"(r0a + 32));
            asm volatile("ld.shared.v2.f32 {%0,%1}, [%2];"
                         : "=f"(v3.x), "=f"(v3.y) : "r"(r1a + 32));
            unsigned a[4];
            a[0] = packh2(v0.x, v0.y);
            a[1] = packh2(v1.x, v1.y);
            a[2] = packh2(v2.x, v2.y);
            a[3] = packh2(v3.x, v3.y);

            const uint4* bp = bp_lane + (size_t)(c * 2 + ks2) * NJ * 32;
#pragma unroll
            for (int j = 0; j < NJ; j++) {
                uint4 b = bp[j * 32];
                unsigned bhi[2] = {b.x, b.y};
                unsigned blo[2] = {b.z, b.w};
                mma_f16(acc[j], a, bhi);
                mma_f16(acc[j], a, blo);
            }
        }

        __syncwarp();                       // all lanes done reading stage
        if (c + 2 < NCH) issue(c + 2);
        cp_commit();
    }

    // ---- epilogue: write P ----
    size_t o0 = (size_t)(row0 + g) * NPAD;
    size_t o1 = (size_t)(row0 + g + 8) * NPAD;
#pragma unroll
    for (int j = 0; j < NJ; j++) {
        int col = j * 8 + th * 2;
        *(float2*)&g_P[o0 + col] = make_float2(acc[j][0], acc[j][1]);
        *(float2*)&g_P[o1 + col] = make_float2(acc[j][2], acc[j][3]);
    }
}

// ---------------- K2: per-bag softmax + combine over P ---------------------
__global__ __launch_bounds__(256) void k_bags(const int* __restrict__ scope,
                                              const int* __restrict__ labels,
                                              const float* __restrict__ bias,
                                              float* __restrict__ out) {
    __shared__ float wbuf[8][WCAP];
    int wid = threadIdx.x >> 5, lane = threadIdx.x & 31;
    int bag = blockIdx.x * 8 + wid;
    if (bag >= NBAGS) return;
    int s = scope[2 * bag];
    int e = scope[2 * bag + 1];
    int c = e - s;
    float* w = (c <= WCAP) ? wbuf[wid] : (g_wglob + s);

    float m = -FLT_MAX;
    for (int i = lane; i < c; i += 32) {
        int gi = s + i;
        float lg = g_P[(size_t)gi * NPAD + labels[gi]];
        w[i] = lg;
        m = fmaxf(m, lg);
    }
#pragma unroll
    for (int o = 16; o; o >>= 1) m = fmaxf(m, __shfl_xor_sync(0xffffffffu, m, o));

    float sum = 0.f;
    for (int i = lane; i < c; i += 32) {
        float ev = __expf(w[i] - m);
        w[i] = ev;
        sum += ev;
    }
#pragma unroll
    for (int o = 16; o; o >>= 1) sum += __shfl_xor_sync(0xffffffffu, sum, o);
    float inv = 1.f / sum;
    __syncwarp();

    int col = lane * 2;
    if (col < NPAD) {    // lanes 0..27
        float2 o2 = make_float2(0.f, 0.f);
        const float* pbase = g_P + (size_t)s * NPAD + col;
#pragma unroll 8
        for (int i = 0; i < c; i++) {
            float wi = w[i] * inv;
            float2 p2 = *(const float2*)(pbase + (size_t)i * NPAD);
            o2.x = fmaf(wi, p2.x, o2.x);
            o2.y = fmaf(wi, p2.y, o2.y);
        }
        if (col < NREL)     out[(size_t)bag * NREL + col]     = o2.x + bias[col];
        if (col + 1 < NREL) out[(size_t)bag * NREL + col + 1] = o2.y + bias[col + 1];
    }
}

// ---------------- launch ----------------
extern "C" void kernel_launch(void* const* d_in, const int* in_sizes, int n_in,
                              void* d_out, int out_size) {
    const float* repre  = (const float*)d_in[0];   // [N, D]
    const float* rel    = (const float*)d_in[1];   // [R, D]
    const float* bias   = (const float*)d_in[2];   // [R]
    const int* scope    = (const int*)d_in[3];     // [NBAGS, 2] int32
    const int* labels   = (const int*)d_in[4];     // [N]        int32
    float* out = (float*)d_out;                    // [NBAGS, R]

    (void)in_sizes; (void)n_in; (void)out_size;

    k_prep<<<(NKS * NJ * 32 + 255) / 256, 256>>>(rel);
    int nstrips = NROWS / 16;                       // 12500
    k_pgemm<<<(nstrips + 7) / 8, 256>>>(repre);
    k_bags<<<(NBAGS + 7) / 8, 256>>>(scope, labels, bias, out);
}